// round 2
// baseline (speedup 1.0000x reference)
#include <cuda_runtime.h>

// BilateralFilter: x [32, 3, 64, 512] f32 -> out [32, 4, 14, 64, 512] f32
// out[b, cls, k, z, a] = exp(-sqdist(b,k,z,a) * inv2theta2[cls])
// sqdist = sum_ch (x[b,ch,z,a] - nbr_k(x)[b,ch,z,a])^2, zero-padded 3x5
// neighborhood excluding center (K=14, dz-major/da-minor order).
// inv2theta2 = [2222.2222, 2222.2222, 5000, 5000] -> cls {0,1} identical,
// cls {2,3} identical, and 5000 = 2.25 * 2222.2222.

#define BZ 32
#define ZZ 64
#define AA 512
#define PLANE (ZZ * AA)          // 32768

__global__ __launch_bounds__(256)
void bilateral_kernel(const float* __restrict__ x, float* __restrict__ out) {
    int tid = blockIdx.x * blockDim.x + threadIdx.x;
    // total threads = 32 * 64 * (512/4) = 262144
    int a4 = tid & 127;            // group of 4 along azimuth
    int z  = (tid >> 7) & 63;
    int b  = tid >> 13;
    int a0 = a4 << 2;

    const bool interior = (a4 != 0) & (a4 != 127);

    // Accumulated squared distances for the 14 neighbor offsets x 4 pixels.
    float4 sq[14];
#pragma unroll
    for (int k = 0; k < 14; k++) sq[k] = make_float4(0.f, 0.f, 0.f, 0.f);

#pragma unroll
    for (int ch = 0; ch < 3; ch++) {
        const float* base = x + ((b * 3 + ch) * PLANE);
        // 3 rows (z-1, z, z+1) x 8 cols (a0-2 .. a0+5), zero-padded.
        float win[3][8];
#pragma unroll
        for (int r = 0; r < 3; r++) {
            int zr = z - 1 + r;
            bool zok = (zr >= 0) & (zr < ZZ);
            const float* row = base + (zr << 9);
            if (zok & interior) {
                // Common case: fully unguarded loads.
                float4 v = *reinterpret_cast<const float4*>(row + a0);
                win[r][2] = v.x; win[r][3] = v.y; win[r][4] = v.z; win[r][5] = v.w;
                win[r][0] = row[a0 - 2];
                win[r][1] = row[a0 - 1];
                win[r][6] = row[a0 + 4];
                win[r][7] = row[a0 + 5];
            } else if (zok) {
                float4 v = *reinterpret_cast<const float4*>(row + a0);
                win[r][2] = v.x; win[r][3] = v.y; win[r][4] = v.z; win[r][5] = v.w;
                win[r][0] = (a0 >= 2)     ? row[a0 - 2] : 0.f;
                win[r][1] = (a0 >= 1)     ? row[a0 - 1] : 0.f;
                win[r][6] = (a0 + 4 < AA) ? row[a0 + 4] : 0.f;
                win[r][7] = (a0 + 5 < AA) ? row[a0 + 5] : 0.f;
            } else {
#pragma unroll
                for (int j = 0; j < 8; j++) win[r][j] = 0.f;
            }
        }
        // Center values for the 4 pixels: win[1][2..5]
        float c0 = win[1][2], c1 = win[1][3], c2 = win[1][4], c3 = win[1][5];
        int k = 0;
#pragma unroll
        for (int dz = 0; dz < 3; dz++) {
#pragma unroll
            for (int da = 0; da < 5; da++) {
                if (dz == 1 && da == 2) continue;   // center excluded
                float d0 = c0 - win[dz][0 + da];
                float d1 = c1 - win[dz][1 + da];
                float d2 = c2 - win[dz][2 + da];
                float d3 = c3 - win[dz][3 + da];
                sq[k].x += d0 * d0;
                sq[k].y += d1 * d1;
                sq[k].z += d2 * d2;
                sq[k].w += d3 * d3;
                k++;
            }
        }
    }

    const float C1 = 2222.2222f;      // 1 / (2 * 0.015^2); 5000 = 2.25 * C1
    float* ob = out + (size_t)b * (4 * 14 * PLANE) + (z << 9) + a0;

#pragma unroll
    for (int k = 0; k < 14; k++) {
        float4 s = sq[k];
        float t0 = -C1 * s.x, t1 = -C1 * s.y, t2 = -C1 * s.z, t3 = -C1 * s.w;
        float tmax = fmaxf(fmaxf(t0, t1), fmaxf(t2, t3));
        float4 e1 = make_float4(0.f, 0.f, 0.f, 0.f);
        float4 e2 = make_float4(0.f, 0.f, 0.f, 0.f);
        // exp underflows to 0 below ~-87.3; with N(0,1) inputs this branch is
        // skipped by ~88% of warp-iterations, keeping MUFU off the critical path.
        if (tmax > -88.0f) {
            e1.x = __expf(t0);          e1.y = __expf(t1);
            e1.z = __expf(t2);          e1.w = __expf(t3);
            e2.x = __expf(2.25f * t0);  e2.y = __expf(2.25f * t1);
            e2.z = __expf(2.25f * t2);  e2.w = __expf(2.25f * t3);
        }
        float* p = ob + k * PLANE;
        *reinterpret_cast<float4*>(p)                  = e1;  // class 0
        *reinterpret_cast<float4*>(p + 14 * PLANE)     = e1;  // class 1
        *reinterpret_cast<float4*>(p + 28 * PLANE)     = e2;  // class 2
        *reinterpret_cast<float4*>(p + 42 * PLANE)     = e2;  // class 3
    }
}

extern "C" void kernel_launch(void* const* d_in, const int* in_sizes, int n_in,
                              void* d_out, int out_size) {
    const float* x = (const float*)d_in[0];
    float* out = (float*)d_out;
    int total = BZ * ZZ * (AA / 4);          // 262144 threads
    int threads = 256;
    bilateral_kernel<<<total / threads, threads>>>(x, out);
}

// round 3
// speedup vs baseline: 1.2526x; 1.2526x over previous
#include <cuda_runtime.h>

// BilateralFilter: x [32, 3, 64, 512] f32 -> out [32, 4, 14, 64, 512] f32
// out[b, cls, k, z, a] = exp(-sqdist(b,k,z,a) * inv2theta2[cls])
// sqdist = sum_ch (x[b,ch,z,a] - nbr_k(x)[b,ch,z,a])^2, zero-padded 3x5
// neighborhood excluding center (K=14, dz-major/da-minor order).
// inv2theta2 = [2222.2222, 2222.2222, 5000, 5000] -> cls {0,1} == cls {2,3}
// up to 5000 = 2.25 * 2222.2222.
//
// R3 restructure: dz-outer loop so only ONE sq accumulator is live at a time
// (was 14 float4 = 56 regs) -> higher occupancy; __stcs streaming stores so
// the 235MB output stream doesn't evict the 12.6MB input from L2.

#define BZ 32
#define ZZ 64
#define AA 512
#define PLANE (ZZ * AA)          // 32768

__global__ __launch_bounds__(256)
void bilateral_kernel(const float* __restrict__ x, float* __restrict__ out) {
    int tid = blockIdx.x * blockDim.x + threadIdx.x;
    // total threads = 32 * 64 * (512/4) = 262144
    int a4 = tid & 127;            // group of 4 along azimuth
    int z  = (tid >> 7) & 63;
    int b  = tid >> 13;
    int a0 = a4 << 2;

    const bool interior = (a4 != 0) & (a4 != 127);
    const float C1 = 2222.2222f;      // 1/(2*0.015^2); 5000 = 2.25 * C1

    // Center quads per channel (4 pixels each).
    float c0[3], c1[3], c2[3], c3[3];
#pragma unroll
    for (int ch = 0; ch < 3; ch++) {
        const float4 v = *reinterpret_cast<const float4*>(
            x + ((b * 3 + ch) * PLANE) + (z << 9) + a0);
        c0[ch] = v.x; c1[ch] = v.y; c2[ch] = v.z; c3[ch] = v.w;
    }

    float* ob = out + (size_t)b * (4 * 14 * PLANE) + (z << 9) + a0;
    int k = 0;

#pragma unroll
    for (int dz = 0; dz < 3; dz++) {
        int zr = z - 1 + dz;
        bool zok = (zr >= 0) & (zr < ZZ);

        // 8-wide window row (a0-2 .. a0+5) for each channel, zero-padded.
        float win[3][8];
#pragma unroll
        for (int ch = 0; ch < 3; ch++) {
            const float* row = x + ((b * 3 + ch) * PLANE) + (zr << 9);
            if (zok & interior) {
                float4 v = *reinterpret_cast<const float4*>(row + a0);
                win[ch][2] = v.x; win[ch][3] = v.y; win[ch][4] = v.z; win[ch][5] = v.w;
                win[ch][0] = row[a0 - 2];
                win[ch][1] = row[a0 - 1];
                win[ch][6] = row[a0 + 4];
                win[ch][7] = row[a0 + 5];
            } else if (zok) {
                float4 v = *reinterpret_cast<const float4*>(row + a0);
                win[ch][2] = v.x; win[ch][3] = v.y; win[ch][4] = v.z; win[ch][5] = v.w;
                win[ch][0] = (a0 >= 2)     ? row[a0 - 2] : 0.f;
                win[ch][1] = (a0 >= 1)     ? row[a0 - 1] : 0.f;
                win[ch][6] = (a0 + 4 < AA) ? row[a0 + 4] : 0.f;
                win[ch][7] = (a0 + 5 < AA) ? row[a0 + 5] : 0.f;
            } else {
#pragma unroll
                for (int j = 0; j < 8; j++) win[ch][j] = 0.f;
            }
        }

#pragma unroll
        for (int da = 0; da < 5; da++) {
            if (dz == 1 && da == 2) continue;   // center excluded

            float sx = 0.f, sy = 0.f, sz = 0.f, sw = 0.f;
#pragma unroll
            for (int ch = 0; ch < 3; ch++) {
                float d0 = c0[ch] - win[ch][0 + da];
                float d1 = c1[ch] - win[ch][1 + da];
                float d2 = c2[ch] - win[ch][2 + da];
                float d3 = c3[ch] - win[ch][3 + da];
                sx += d0 * d0; sy += d1 * d1; sz += d2 * d2; sw += d3 * d3;
            }

            float t0 = -C1 * sx, t1 = -C1 * sy, t2 = -C1 * sz, t3 = -C1 * sw;
            float tmax = fmaxf(fmaxf(t0, t1), fmaxf(t2, t3));
            float4 e1 = make_float4(0.f, 0.f, 0.f, 0.f);
            float4 e2 = make_float4(0.f, 0.f, 0.f, 0.f);
            // expf underflows to 0 below ~-87.3; with N(0,1) inputs ~88% of
            // warp-iterations skip the MUFU work entirely.
            if (tmax > -88.0f) {
                e1.x = __expf(t0);          e1.y = __expf(t1);
                e1.z = __expf(t2);          e1.w = __expf(t3);
                e2.x = __expf(2.25f * t0);  e2.y = __expf(2.25f * t1);
                e2.z = __expf(2.25f * t2);  e2.w = __expf(2.25f * t3);
            }
            float* p = ob + k * PLANE;
            __stcs(reinterpret_cast<float4*>(p),              e1);  // class 0
            __stcs(reinterpret_cast<float4*>(p + 14 * PLANE), e1);  // class 1
            __stcs(reinterpret_cast<float4*>(p + 28 * PLANE), e2);  // class 2
            __stcs(reinterpret_cast<float4*>(p + 42 * PLANE), e2);  // class 3
            k++;
        }
    }
}

extern "C" void kernel_launch(void* const* d_in, const int* in_sizes, int n_in,
                              void* d_out, int out_size) {
    const float* x = (const float*)d_in[0];
    float* out = (float*)d_out;
    int total = BZ * ZZ * (AA / 4);          // 262144 threads
    int threads = 256;
    bilateral_kernel<<<total / threads, threads>>>(x, out);
}